// round 13
// baseline (speedup 1.0000x reference)
#include <cuda_runtime.h>
#include <cuda_bf16.h>
#include <cstdint>

// ContinuousEmbedding: out[b,f,:] = sum_k weight[k,:] / (|idx(x[b,f]) - k| + 1)
// = 64x64 table T (16 KB = 1024 float4) indexed by bucket.
//
// R13 = R12 (single kernel, builder blocks + backoff spin) with the fan-out
// stores converted to 256-bit st.global.v8.f32 (sm_100+). All STG.128
// variants pinned at ~23us because the per-SM LSU issue bill (16 x 12cyc
// store issue per 8KB tile) is shared and occupancy-independent; STG.256
// halves the store instruction count.

#define NUM_BINS 63
#define KDIM 64          // NUM_BINS + 1
#define EMB_DIM 64
#define NBUILD 8         // builder blocks: 8 x 128 float4 entries

__device__ float g_table[KDIM * EMB_DIM];   // 4096 floats = 1024 float4
__device__ int   g_ready;                   // builders done (0..NBUILD)
__device__ int   g_done;                    // blocks finished (for reset)

__global__ void __launch_bounds__(256, 4)
embed_fused(const float* __restrict__ x,
            const float* __restrict__ low,     // [64]; low[0]=-inf, bins=low[1..]
            const float* __restrict__ weight,  // [64*64]
            float4* __restrict__ out,
            int n_rows)
{
    const int tid = threadIdx.x;
    const int bid = blockIdx.x;

    // ---- phase 1a: builder blocks compute 128 table entries each ----------
    if (bid < NBUILD) {
        __shared__ float srecip[KDIM];
        if (tid < KDIM) srecip[tid] = 1.0f / (float)(tid + 1);
        __syncthreads();
        if (tid < 128) {
            const int e = bid * 128 + tid;     // float4 entry 0..1023
            const int r = e >> 4;              // 0..63
            const int c = e & 15;              // 0..15
            const float4* w4 = reinterpret_cast<const float4*>(weight);
            float4 acc = make_float4(0.f, 0.f, 0.f, 0.f);
#pragma unroll 16
            for (int k = 0; k < KDIM; ++k) {
                int d = r - k; if (d < 0) d = -d;
                const float  s = srecip[d];
                const float4 w = __ldg(w4 + k * 16 + c);
                acc.x = fmaf(w.x, s, acc.x);
                acc.y = fmaf(w.y, s, acc.y);
                acc.z = fmaf(w.z, s, acc.z);
                acc.w = fmaf(w.w, s, acc.w);
            }
            reinterpret_cast<float4*>(g_table)[e] = acc;
        }
        __threadfence();                       // table writes visible (gpu scope)
        __syncthreads();
        if (tid == 0) atomicAdd(&g_ready, 1);
    }

    // ---- phase 1b (all blocks): bucket index, overlapped with build -------
    const int lane = tid & 31;
    const int warp = tid >> 5;
    const int base = (bid * 8 + warp) * 32;
    const bool active = (base < n_rows);

    // g = #{ j : bins[j] < x }: arithmetic guess (bins ~ linspace(-3.1,3.1))
    // then EXACT fixup against the real bin values (low[g] == bins[g-1]).
    int g = 0;
    if (active && base + lane < n_rows) {
        const float xv = __ldg(x + base + lane);
        g = (int)floorf((xv + 3.1f) * 10.0f) + 1;
        g = max(0, min(NUM_BINS, g));
        while (g > 0 && !(xv > __ldg(low + g))) --g;
        while (g < NUM_BINS && (xv > __ldg(low + g + 1))) ++g;
    }

    // ---- phase 2: wait for the table (backoff spin) ------------------------
    if (tid == 0) {
        int r;
        asm volatile("ld.global.acquire.gpu.b32 %0, [%1];"
                     : "=r"(r) : "l"(&g_ready) : "memory");
        while (r < NBUILD) {
            __nanosleep(256);
            asm volatile("ld.global.acquire.gpu.b32 %0, [%1];"
                         : "=r"(r) : "l"(&g_ready) : "memory");
        }
    }
    __syncthreads();

    // ---- phase 3: fan-out with 256-bit stores ------------------------------
    if (active) {
        const float4* table = reinterpret_cast<const float4*>(g_table);
        const bool full = (base + 32 <= n_rows);   // uniform within warp

        if (full) {
            // Each STG.256 covers 4 rows (1024B): lane quarter q -> row 4i+q,
            // slot s = lane&7 -> floats 8s..8s+7 of that row (2 table float4).
            const int q = lane >> 3;
            const int s = lane & 7;
            float* const obase = reinterpret_cast<float*>(out)
                               + (size_t)base * EMB_DIM + lane * 8;
#pragma unroll
            for (int h = 0; h < 2; ++h) {      // 2 batches of 4 stores
                int    idxs[4];
                float4 a[4], b[4];
#pragma unroll
                for (int j = 0; j < 4; ++j)
                    idxs[j] = __shfl_sync(0xffffffffu, g, (h * 4 + j) * 4 + q);
#pragma unroll
                for (int j = 0; j < 4; ++j) {
                    a[j] = __ldg(&table[(idxs[j] << 4) + 2 * s]);
                    b[j] = __ldg(&table[(idxs[j] << 4) + 2 * s + 1]);
                }
#pragma unroll
                for (int j = 0; j < 4; ++j) {
                    float* addr = obase + (size_t)(h * 4 + j) * 4 * EMB_DIM;
                    asm volatile(
                        "st.global.cs.v8.f32 [%0], {%1,%2,%3,%4,%5,%6,%7,%8};"
                        :: "l"(addr),
                           "f"(a[j].x), "f"(a[j].y), "f"(a[j].z), "f"(a[j].w),
                           "f"(b[j].x), "f"(b[j].y), "f"(b[j].z), "f"(b[j].w)
                        : "memory");
                }
            }
        } else {
            // partial tile: guarded float4 stores (rare path)
            const int half = lane >> 4;
            const int part = lane & 15;
#pragma unroll
            for (int j = 0; j < 16; ++j) {
                const int idx = __shfl_sync(0xffffffffu, g, 2 * j + half);
                const float4 v = __ldg(&table[(idx << 4) + part]);
                const int r = base + 2 * j + half;
                if (r < n_rows)
                    __stcs(&out[(size_t)r * 16 + part], v);
            }
        }
    }

    // ---- phase 4: self-reset so every launch is identical ------------------
    __syncthreads();
    if (tid == 0) {
        const int prev = atomicAdd(&g_done, 1);
        if (prev == (int)gridDim.x - 1) {      // last block: reset protocol
            atomicExch(&g_done, 0);
            atomicExch(&g_ready, 0);
        }
    }
}

extern "C" void kernel_launch(void* const* d_in, const int* in_sizes, int n_in,
                              void* d_out, int out_size) {
    const float* x      = (const float*)d_in[0];   // [B*F]
    const float* low    = (const float*)d_in[1];   // [64]
    // d_in[2] = high [64] (redundant with low for the bucket computation)
    const float* weight = (const float*)d_in[3];   // [64*64]

    float4* out = (float4*)d_out;
    const int n_rows = out_size / EMB_DIM;         // 524288

    // One-shot grid: 8 warps x 32 rows per block. At least NBUILD blocks.
    int blocks = (n_rows + 255) / 256;             // 2048 for the real shape
    if (blocks < NBUILD) blocks = NBUILD;

    embed_fused<<<blocks, 256>>>(x, low, weight, out, n_rows);
}

// round 14
// speedup vs baseline: 1.1171x; 1.1171x over previous
#include <cuda_runtime.h>
#include <cuda_bf16.h>
#include <cstdint>

// ContinuousEmbedding: out[b,f,:] = sum_k weight[k,:] / (|idx(x[b,f]) - k| + 1)
// = 64x64 table T (16 KB = 1024 float4) indexed by bucket.
//
// R14 = R12 (best: single kernel, 8 builder blocks + backoff spin, 8-deep
// batched STG.128.cs fan-out) with the schedule changed: 740 persistent
// blocks (one full resident wave at occ 5/SM), grid-stride over tiles, and
// software-pipelined x loads (next tile's x issued before current tile's
// stores) so the 577-cyc DRAM latency and the build-spin are paid once.

#define NUM_BINS 63
#define KDIM 64          // NUM_BINS + 1
#define EMB_DIM 64
#define NBUILD 8         // builder blocks: 8 x 128 float4 entries

__device__ float g_table[KDIM * EMB_DIM];   // 4096 floats = 1024 float4
__device__ int   g_ready;                   // builders done (0..NBUILD)
__device__ int   g_done;                    // blocks finished (for reset)

__device__ __forceinline__ int bucket_of(float xv, const float* __restrict__ low) {
    // g = #{ j : bins[j] < x }: arithmetic guess (bins ~ linspace(-3.1,3.1))
    // then EXACT fixup against the real bin values (low[g] == bins[g-1]).
    int g = (int)floorf((xv + 3.1f) * 10.0f) + 1;
    g = max(0, min(NUM_BINS, g));
    while (g > 0 && !(xv > __ldg(low + g))) --g;
    while (g < NUM_BINS && (xv > __ldg(low + g + 1))) ++g;
    return g;
}

__global__ void __launch_bounds__(256, 5)
embed_fused(const float* __restrict__ x,
            const float* __restrict__ low,     // [64]; low[0]=-inf, bins=low[1..]
            const float* __restrict__ weight,  // [64*64]
            float4* __restrict__ out,
            int n_rows)
{
    const int tid = threadIdx.x;
    const int bid = blockIdx.x;

    // ---- builders: blocks 0..7 compute 128 table entries each -------------
    if (bid < NBUILD) {
        __shared__ float srecip[KDIM];
        if (tid < KDIM) srecip[tid] = 1.0f / (float)(tid + 1);
        __syncthreads();
        if (tid < 128) {
            const int e = bid * 128 + tid;     // float4 entry 0..1023
            const int r = e >> 4;
            const int c = e & 15;
            const float4* w4 = reinterpret_cast<const float4*>(weight);
            float4 acc = make_float4(0.f, 0.f, 0.f, 0.f);
#pragma unroll 16
            for (int k = 0; k < KDIM; ++k) {
                int d = r - k; if (d < 0) d = -d;
                const float  s = srecip[d];
                const float4 w = __ldg(w4 + k * 16 + c);
                acc.x = fmaf(w.x, s, acc.x);
                acc.y = fmaf(w.y, s, acc.y);
                acc.z = fmaf(w.z, s, acc.z);
                acc.w = fmaf(w.w, s, acc.w);
            }
            reinterpret_cast<float4*>(g_table)[e] = acc;
        }
        __threadfence();                       // table writes visible (gpu scope)
        __syncthreads();
        if (tid == 0) atomicAdd(&g_ready, 1);
    }

    // ---- persistent fan-out over 32-row tiles ------------------------------
    const int lane = tid & 31;
    const int warp = tid >> 5;
    const int half = lane >> 4;        // row-within-pair
    const int part = lane & 15;        // float4 slot within a 64-float row
    const int gw = bid * 8 + warp;
    const int nw = gridDim.x * 8;
    const int n_tiles = (n_rows + 31) >> 5;

    // first tile's x load + bucket compute, overlapped with the build
    int  tile = gw;
    float xv = 0.0f;
    if (tile < n_tiles && tile * 32 + lane < n_rows)
        xv = __ldg(x + tile * 32 + lane);
    int g = bucket_of(xv, low);

    // wait for the table (backoff spin, low L2 pressure)
    if (tid == 0) {
        int r;
        asm volatile("ld.global.acquire.gpu.b32 %0, [%1];"
                     : "=r"(r) : "l"(&g_ready) : "memory");
        while (r < NBUILD) {
            __nanosleep(256);
            asm volatile("ld.global.acquire.gpu.b32 %0, [%1];"
                         : "=r"(r) : "l"(&g_ready) : "memory");
        }
    }
    __syncthreads();

    const float4* table = reinterpret_cast<const float4*>(g_table);

    for (; tile < n_tiles; tile += nw) {
        const int base = tile << 5;

        // prefetch next tile's x (hides DRAM latency behind current stores)
        const int nxt = tile + nw;
        float xv_n = 0.0f;
        if (nxt < n_tiles && (nxt << 5) + lane < n_rows)
            xv_n = __ldg(x + (nxt << 5) + lane);

        const bool full = (base + 32 <= n_rows);   // uniform within warp
#pragma unroll
        for (int h = 0; h < 2; ++h) {
            int    idxs[8];
            float4 v[8];
#pragma unroll
            for (int j = 0; j < 8; ++j)
                idxs[j] = __shfl_sync(0xffffffffu, g, (h * 8 + j) * 2 + half);
#pragma unroll
            for (int j = 0; j < 8; ++j)
                v[j] = __ldg(&table[(idxs[j] << 4) + part]);
            if (full) {
#pragma unroll
                for (int j = 0; j < 8; ++j)
                    __stcs(&out[(size_t)(base + (h * 8 + j) * 2) * 16 + lane], v[j]);
            } else {
#pragma unroll
                for (int j = 0; j < 8; ++j) {
                    const int r = base + (h * 8 + j) * 2 + half;
                    if (r < n_rows)
                        __stcs(&out[(size_t)r * 16 + part], v[j]);
                }
            }
        }

        g = bucket_of(xv_n, low);              // compute next tile's bucket
    }

    // ---- self-reset so every launch is identical ---------------------------
    __syncthreads();
    if (tid == 0) {
        const int prev = atomicAdd(&g_done, 1);
        if (prev == (int)gridDim.x - 1) {      // last block: reset protocol
            atomicExch(&g_done, 0);
            atomicExch(&g_ready, 0);
        }
    }
}

extern "C" void kernel_launch(void* const* d_in, const int* in_sizes, int n_in,
                              void* d_out, int out_size) {
    const float* x      = (const float*)d_in[0];   // [B*F]
    const float* low    = (const float*)d_in[1];   // [64]
    // d_in[2] = high [64] (redundant with low for the bucket computation)
    const float* weight = (const float*)d_in[3];   // [64*64]

    float4* out = (float4*)d_out;
    const int n_rows = out_size / EMB_DIM;         // 524288

    // 740 = 148 SMs x 5 resident blocks: exactly one wave, persistent.
    const int n_tiles = (n_rows + 31) / 32;
    int blocks = 740;
    int need = (n_tiles + 7) / 8;
    if (blocks > need) blocks = need;
    if (blocks < NBUILD) blocks = NBUILD;

    embed_fused<<<blocks, 256>>>(x, low, weight, out, n_rows);
}